// round 1
// baseline (speedup 1.0000x reference)
#include <cuda_runtime.h>
#include <math.h>

// ---------------------------------------------------------------------------
// Shapes (fixed): B=8, N=1024, C=768, H=8, D=96, Q=8
// ---------------------------------------------------------------------------

// Scratch buffers (allocation-free rule: __device__ globals)
__device__ float g_qkv[8192 * 2304];          // [B*N, 3*C]  (B,N,3,H,D)
__device__ float g_eq[65536 * 16];            // embed(q) raw e vector per token
__device__ float g_ek[65536 * 16];            // embed(k)
__device__ float g_scores[67108864];          // [B*H, 1024, 1024]
__device__ float g_quantum[8192 * 768];       // [B,N,C]
__device__ float g_classical[8192 * 768];     // [B,N,C]
__device__ float g_fused[8192 * 768];
__device__ float g_y[8192 * 768];
__device__ float g_xmean[8 * 768];
__device__ float g_fw[8 * 768];

// ---------------------------------------------------------------------------
// Generic 128x128x16 SGEMM (row-major NN), optional bias (per-col) + residual.
// Requires: M%128==0, N%128==0, K%16==0, lda/ldb multiples of 4.
// ---------------------------------------------------------------------------
__global__ void sgemm128(const float* __restrict__ A, const float* __restrict__ B,
                         const float* __restrict__ bias, const float* __restrict__ resid,
                         float* __restrict__ C, int K, int lda, int ldb, int ldc)
{
    __shared__ float As[16][132];
    __shared__ float Bs[16][132];
    const int tid = threadIdx.x;
    const int tx = tid & 15, ty = tid >> 4;
    const size_t rowBase = (size_t)blockIdx.y * 128;
    const size_t colBase = (size_t)blockIdx.x * 128;

    float acc[8][8];
#pragma unroll
    for (int i = 0; i < 8; i++)
#pragma unroll
        for (int j = 0; j < 8; j++) acc[i][j] = 0.f;

    for (int k0 = 0; k0 < K; k0 += 16) {
#pragma unroll
        for (int i = 0; i < 2; i++) {
            int s = tid + i * 256;
            int r = s >> 2, c = (s & 3) << 2;
            float4 va = *(const float4*)(A + (rowBase + r) * lda + k0 + c);
            As[c + 0][r] = va.x; As[c + 1][r] = va.y;
            As[c + 2][r] = va.z; As[c + 3][r] = va.w;
            int rb = s >> 5, cb = (s & 31) << 2;
            float4 vb = *(const float4*)(B + (size_t)(k0 + rb) * ldb + colBase + cb);
            *(float4*)&Bs[rb][cb] = vb;
        }
        __syncthreads();
#pragma unroll
        for (int kk = 0; kk < 16; kk++) {
            float a[8], b[8];
#pragma unroll
            for (int i = 0; i < 8; i++) a[i] = As[kk][ty * 8 + i];
#pragma unroll
            for (int j = 0; j < 8; j++) b[j] = Bs[kk][tx * 8 + j];
#pragma unroll
            for (int i = 0; i < 8; i++)
#pragma unroll
                for (int j = 0; j < 8; j++) acc[i][j] += a[i] * b[j];
        }
        __syncthreads();
    }
#pragma unroll
    for (int i = 0; i < 8; i++) {
        size_t row = rowBase + ty * 8 + i;
#pragma unroll
        for (int j = 0; j < 8; j++) {
            size_t col = colBase + tx * 8 + j;
            float v = acc[i][j];
            if (bias)  v += bias[col];
            if (resid) v += resid[row * ldc + col];
            C[row * ldc + col] = v;
        }
    }
}

// ---------------------------------------------------------------------------
// scores[bh,n,m] = scale * sum_d q[b,h,n,d] * k[b,h,m,d]   (batched NT GEMM)
// ---------------------------------------------------------------------------
__global__ void scores_kernel(const float* __restrict__ qkv, float* __restrict__ scores)
{
    __shared__ float As[16][132];
    __shared__ float Bs[16][132];
    const int bh = blockIdx.z, b = bh >> 3, h = bh & 7;
    const float* qp = qkv + (size_t)b * 1024 * 2304 + h * 96;
    const float* kp = qp + 768;
    float* out = scores + (size_t)bh * 1024 * 1024;
    const int tid = threadIdx.x, tx = tid & 15, ty = tid >> 4;
    const int rowBase = blockIdx.y * 128, colBase = blockIdx.x * 128;

    float acc[8][8];
#pragma unroll
    for (int i = 0; i < 8; i++)
#pragma unroll
        for (int j = 0; j < 8; j++) acc[i][j] = 0.f;

    for (int k0 = 0; k0 < 96; k0 += 16) {
#pragma unroll
        for (int i = 0; i < 2; i++) {
            int s = tid + i * 256;
            int r = s >> 2, c = (s & 3) << 2;
            float4 va = *(const float4*)(qp + (size_t)(rowBase + r) * 2304 + k0 + c);
            As[c + 0][r] = va.x; As[c + 1][r] = va.y;
            As[c + 2][r] = va.z; As[c + 3][r] = va.w;
            float4 vb = *(const float4*)(kp + (size_t)(colBase + r) * 2304 + k0 + c);
            Bs[c + 0][r] = vb.x; Bs[c + 1][r] = vb.y;
            Bs[c + 2][r] = vb.z; Bs[c + 3][r] = vb.w;
        }
        __syncthreads();
#pragma unroll
        for (int kk = 0; kk < 16; kk++) {
            float a[8], bb[8];
#pragma unroll
            for (int i = 0; i < 8; i++) a[i] = As[kk][ty * 8 + i];
#pragma unroll
            for (int j = 0; j < 8; j++) bb[j] = Bs[kk][tx * 8 + j];
#pragma unroll
            for (int i = 0; i < 8; i++)
#pragma unroll
                for (int j = 0; j < 8; j++) acc[i][j] += a[i] * bb[j];
        }
        __syncthreads();
    }
    const float scale = 0.10206207261596575f;  // 96^-0.5
#pragma unroll
    for (int i = 0; i < 8; i++) {
        size_t row = rowBase + ty * 8 + i;
#pragma unroll
        for (int j = 0; j < 8; j++) {
            size_t col = colBase + tx * 8 + j;
            out[row * 1024 + col] = acc[i][j] * scale;
        }
    }
}

// ---------------------------------------------------------------------------
// Row softmax over 1024 elements, in place. One block (256 thr) per row.
// ---------------------------------------------------------------------------
__global__ void softmax1024(float* __restrict__ scores)
{
    float* row = scores + (size_t)blockIdx.x * 1024;
    const int tid = threadIdx.x, lane = tid & 31, warp = tid >> 5;
    __shared__ float sred[8];
    __shared__ float sbc;

    float v[4];
    float mx = -1e30f;
#pragma unroll
    for (int i = 0; i < 4; i++) { v[i] = row[tid + i * 256]; mx = fmaxf(mx, v[i]); }
#pragma unroll
    for (int o = 16; o; o >>= 1) mx = fmaxf(mx, __shfl_xor_sync(0xffffffffu, mx, o));
    if (lane == 0) sred[warp] = mx;
    __syncthreads();
    if (tid == 0) {
        float m = sred[0];
        for (int i = 1; i < 8; i++) m = fmaxf(m, sred[i]);
        sbc = m;
    }
    __syncthreads();
    mx = sbc;

    float s = 0.f;
#pragma unroll
    for (int i = 0; i < 4; i++) { v[i] = expf(v[i] - mx); s += v[i]; }
#pragma unroll
    for (int o = 16; o; o >>= 1) s += __shfl_xor_sync(0xffffffffu, s, o);
    if (lane == 0) sred[warp] = s;
    __syncthreads();
    if (tid == 0) {
        float m = 0.f;
        for (int i = 0; i < 8; i++) m += sred[i];
        sbc = m;
    }
    __syncthreads();
    float inv = 1.f / sbc;
#pragma unroll
    for (int i = 0; i < 4; i++) row[tid + i * 256] = v[i] * inv;
}

// ---------------------------------------------------------------------------
// classical[b,n,h*96+d] = sum_m P[bh,n,m] * v[b,h,m,d]
// BM=64, BN=96 (full D), BK=16; 256 threads, 4x6 microtile.
// ---------------------------------------------------------------------------
__global__ void pv_kernel(const float* __restrict__ scores, const float* __restrict__ qkv,
                          float* __restrict__ classical)
{
    __shared__ float As[16][68];
    __shared__ float Bs[16][96];
    const int bh = blockIdx.z, b = bh >> 3, h = bh & 7;
    const float* P = scores + (size_t)bh * 1024 * 1024;
    const float* V = qkv + (size_t)b * 1024 * 2304 + 1536 + h * 96;
    float* out = classical + (size_t)b * 1024 * 768 + h * 96;
    const int tid = threadIdx.x, tx = tid & 15, ty = tid >> 4;
    const int rowBase = blockIdx.y * 64;

    float acc[4][6];
#pragma unroll
    for (int i = 0; i < 4; i++)
#pragma unroll
        for (int j = 0; j < 6; j++) acc[i][j] = 0.f;

    for (int k0 = 0; k0 < 1024; k0 += 16) {
        {
            int r = tid >> 2, c = (tid & 3) << 2;
            float4 va = *(const float4*)(P + (size_t)(rowBase + r) * 1024 + k0 + c);
            As[c + 0][r] = va.x; As[c + 1][r] = va.y;
            As[c + 2][r] = va.z; As[c + 3][r] = va.w;
        }
        {
            int r = tid >> 4, cb = (tid & 15) * 6;
#pragma unroll
            for (int u = 0; u < 6; u++)
                Bs[r][cb + u] = V[(size_t)(k0 + r) * 2304 + cb + u];
        }
        __syncthreads();
#pragma unroll
        for (int kk = 0; kk < 16; kk++) {
            float a[4], bb[6];
#pragma unroll
            for (int i = 0; i < 4; i++) a[i] = As[kk][ty * 4 + i];
#pragma unroll
            for (int j = 0; j < 6; j++) bb[j] = Bs[kk][tx * 6 + j];
#pragma unroll
            for (int i = 0; i < 4; i++)
#pragma unroll
                for (int j = 0; j < 6; j++) acc[i][j] += a[i] * bb[j];
        }
        __syncthreads();
    }
#pragma unroll
    for (int i = 0; i < 4; i++) {
        size_t row = rowBase + ty * 4 + i;
#pragma unroll
        for (int j = 0; j < 6; j++)
            out[row * 768 + tx * 6 + j] = acc[i][j];
    }
}

// ---------------------------------------------------------------------------
// Embedding MLP: e = relu(h @ w1 + b1) @ w2 + b2  (h: 96, hid 64, out 16)
// warp per token; which=0 -> q, which=1 -> k slice of qkv.
// ---------------------------------------------------------------------------
__global__ void embed_kernel(const float* __restrict__ qkv,
                             const float* __restrict__ w1, const float* __restrict__ b1,
                             const float* __restrict__ w2, const float* __restrict__ b2,
                             float* __restrict__ eout, int which)
{
    __shared__ float sw1[96 * 64];
    __shared__ float sw2[64 * 16];
    __shared__ float sb1[64];
    __shared__ float sb2[16];
    __shared__ float sh[8][64];
    const int tid = threadIdx.x;
    for (int i = tid; i < 96 * 64; i += 256) sw1[i] = w1[i];
    for (int i = tid; i < 64 * 16; i += 256) sw2[i] = w2[i];
    if (tid < 64) sb1[tid] = b1[tid];
    if (tid < 16) sb2[tid] = b2[tid];
    __syncthreads();

    const int warp = tid >> 5, lane = tid & 31;
    const int t = blockIdx.x * 8 + warp;       // token in [0, 65536)
    const int b = t >> 13, h = (t >> 10) & 7, n = t & 1023;
    const float* xp = qkv + (size_t)(b * 1024 + n) * 2304 + which * 768 + h * 96;
    float x0 = xp[lane], x1 = xp[lane + 32], x2 = xp[lane + 64];

    float acc0 = sb1[lane], acc1 = sb1[lane + 32];
#pragma unroll
    for (int i = 0; i < 32; i++) {
        float xv = __shfl_sync(0xffffffffu, x0, i);
        acc0 += xv * sw1[i * 64 + lane];
        acc1 += xv * sw1[i * 64 + 32 + lane];
    }
#pragma unroll
    for (int i = 0; i < 32; i++) {
        float xv = __shfl_sync(0xffffffffu, x1, i);
        acc0 += xv * sw1[(32 + i) * 64 + lane];
        acc1 += xv * sw1[(32 + i) * 64 + 32 + lane];
    }
#pragma unroll
    for (int i = 0; i < 32; i++) {
        float xv = __shfl_sync(0xffffffffu, x2, i);
        acc0 += xv * sw1[(64 + i) * 64 + lane];
        acc1 += xv * sw1[(64 + i) * 64 + 32 + lane];
    }
    sh[warp][lane] = fmaxf(acc0, 0.f);
    sh[warp][lane + 32] = fmaxf(acc1, 0.f);
    __syncwarp();
    if (lane < 16) {
        float o = sb2[lane];
#pragma unroll
        for (int j = 0; j < 64; j++) o += sh[warp][j] * sw2[j * 16 + lane];
        eout[(size_t)t * 16 + lane] = o;
    }
}

// ---------------------------------------------------------------------------
// Quantum path: state = qq + kk -> variational(2 layers) -> probs -> gumbel
// softmax -> MLP(8->64->96) -> quantum_out = attn_w * v   (warp per token)
// ---------------------------------------------------------------------------
__global__ void quantum_kernel(const float* __restrict__ qkv,
                               const float* __restrict__ eq, const float* __restrict__ ek,
                               const float* __restrict__ gate, const float* __restrict__ ent,
                               const float* __restrict__ mdw1, const float* __restrict__ mdb1,
                               const float* __restrict__ mdw2, const float* __restrict__ mdb2,
                               const float* __restrict__ gumbel, float* __restrict__ quantum)
{
    __shared__ float sw1[8 * 64];
    __shared__ float sw2[64 * 96];
    __shared__ float sb1[64];
    __shared__ float sb2[96];
    __shared__ float sg[48];
    __shared__ float se[14];
    __shared__ float sh[8][64];
    const int tid = threadIdx.x;
    for (int i = tid; i < 8 * 64; i += 256) sw1[i] = mdw1[i];
    for (int i = tid; i < 64 * 96; i += 256) sw2[i] = mdw2[i];
    if (tid < 64) sb1[tid] = mdb1[tid];
    if (tid < 96) sb2[tid] = mdb2[tid];
    if (tid < 48) sg[tid] = gate[tid];
    if (tid < 14) se[tid] = ent[tid];
    __syncthreads();

    const int warp = tid >> 5, lane = tid & 31;
    const int t = blockIdx.x * 8 + warp;
    const int b = t >> 13, h = (t >> 10) & 7, n = t & 1023;

    const float* eqp = eq + (size_t)t * 16;
    const float* ekp = ek + (size_t)t * 16;
    float ev[16];
    float sr[8], si[8];

    // qq
#pragma unroll
    for (int i = 0; i < 16; i++) ev[i] = eqp[i];
    {
        float mx = ev[0];
#pragma unroll
        for (int i = 1; i < 8; i++) mx = fmaxf(mx, ev[i]);
        float a[8]; float ssum = 0.f;
#pragma unroll
        for (int i = 0; i < 8; i++) { a[i] = expf(ev[i] - mx); ssum += a[i]; }
        float inv = 1.f / ssum;
#pragma unroll
        for (int i = 0; i < 8; i++) {
            float amp = a[i] * inv, ph = ev[8 + i];
            sr[i] = amp * cosf(ph);
            si[i] = amp * sinf(ph);
        }
    }
    // + kk
#pragma unroll
    for (int i = 0; i < 16; i++) ev[i] = ekp[i];
    {
        float mx = ev[0];
#pragma unroll
        for (int i = 1; i < 8; i++) mx = fmaxf(mx, ev[i]);
        float a[8]; float ssum = 0.f;
#pragma unroll
        for (int i = 0; i < 8; i++) { a[i] = expf(ev[i] - mx); ssum += a[i]; }
        float inv = 1.f / ssum;
#pragma unroll
        for (int i = 0; i < 8; i++) {
            float amp = a[i] * inv, ph = ev[8 + i];
            sr[i] += amp * cosf(ph);
            si[i] += amp * sinf(ph);
        }
    }

    // variational (depth 2)
#pragma unroll
    for (int l = 0; l < 2; l++) {
        float nr[8], ni[8];
#pragma unroll
        for (int i = 0; i < 8; i++) {
            float ry = sg[(l * 8 + i) * 3 + 1];
            float rz = sg[(l * 8 + i) * 3 + 2];
            float cz = cosf(rz), sz = sinf(rz), f = cosf(ry * 0.5f);
            nr[i] = (sr[i] * cz - si[i] * sz) * f;
            ni[i] = (sr[i] * sz + si[i] * cz) * f;
        }
        sr[0] = nr[0]; si[0] = ni[0];
#pragma unroll
        for (int i = 1; i < 8; i++) {
            float s_ = 1.f / (1.f + expf(-se[l * 7 + i - 1]));
            sr[i] = nr[i] + s_ * nr[i - 1];
            si[i] = ni[i] + s_ * ni[i - 1];
        }
    }

    // probs softmax, gumbel softmax (T=0.5)
    float p[8];
#pragma unroll
    for (int i = 0; i < 8; i++) p[i] = sr[i] * sr[i] + si[i] * si[i];
    float mx = p[0];
#pragma unroll
    for (int i = 1; i < 8; i++) mx = fmaxf(mx, p[i]);
    float ssum = 0.f;
#pragma unroll
    for (int i = 0; i < 8; i++) { p[i] = expf(p[i] - mx); ssum += p[i]; }
    float inv = 1.f / ssum;
    const float* gp = gumbel + (size_t)t * 8;
    float lg[8];
    float mx2 = -1e30f;
#pragma unroll
    for (int i = 0; i < 8; i++) {
        lg[i] = (logf(p[i] * inv + 1e-10f) + gp[i]) * 2.f;
        mx2 = fmaxf(mx2, lg[i]);
    }
    float s2 = 0.f;
#pragma unroll
    for (int i = 0; i < 8; i++) { lg[i] = expf(lg[i] - mx2); s2 += lg[i]; }
    float inv2 = 1.f / s2;
    float meas[8];
#pragma unroll
    for (int i = 0; i < 8; i++) meas[i] = lg[i] * inv2;

    // MLP: 8 -> 64 (relu) -> 96 ; then * v, scatter to [B,N,C]
    float h0 = sb1[lane], h1 = sb1[lane + 32];
#pragma unroll
    for (int q = 0; q < 8; q++) {
        h0 += meas[q] * sw1[q * 64 + lane];
        h1 += meas[q] * sw1[q * 64 + 32 + lane];
    }
    sh[warp][lane] = fmaxf(h0, 0.f);
    sh[warp][lane + 32] = fmaxf(h1, 0.f);
    __syncwarp();

    const float* vp = qkv + (size_t)(b * 1024 + n) * 2304 + 1536 + h * 96;
    float* outp = quantum + (size_t)(b * 1024 + n) * 768 + h * 96;
#pragma unroll
    for (int u = 0; u < 3; u++) {
        int d = lane + u * 32;
        float o = sb2[d];
#pragma unroll
        for (int j = 0; j < 64; j++) o += sh[warp][j] * sw2[j * 96 + d];
        outp[d] = o * vp[d];
    }
}

// ---------------------------------------------------------------------------
// x mean over N, fw = sigmoid(xmean @ w_proj + b_proj), blend, layernorm
// ---------------------------------------------------------------------------
__global__ void xmean_kernel(const float* __restrict__ x, float* __restrict__ xmean)
{
    int idx = blockIdx.x * blockDim.x + threadIdx.x;
    if (idx >= 8 * 768) return;
    int b = idx / 768, c = idx % 768;
    const float* p = x + (size_t)b * 1024 * 768 + c;
    float s = 0.f;
    for (int n = 0; n < 1024; n++) s += p[(size_t)n * 768];
    xmean[idx] = s * (1.f / 1024.f);
}

__global__ void fw_kernel(const float* __restrict__ xmean, const float* __restrict__ wproj,
                          const float* __restrict__ bproj, float* __restrict__ fw)
{
    int idx = blockIdx.x * blockDim.x + threadIdx.x;
    if (idx >= 8 * 768) return;
    int b = idx / 768, j = idx % 768;
    const float* xm = xmean + b * 768;
    float s = bproj[j];
    for (int c = 0; c < 768; c++) s += xm[c] * wproj[(size_t)c * 768 + j];
    fw[idx] = 1.f / (1.f + expf(-s));
}

__global__ void blend_kernel(const float* __restrict__ fw, const float* __restrict__ quant,
                             const float* __restrict__ clas, float* __restrict__ fused)
{
    size_t idx = (size_t)blockIdx.x * blockDim.x + threadIdx.x;
    if (idx >= (size_t)8192 * 768) return;
    int m = (int)(idx / 768);
    int b = m >> 10;
    int c = (int)(idx % 768);
    float f = fw[b * 768 + c];
    fused[idx] = f * quant[idx] + (1.f - f) * clas[idx];
}

__global__ void ln_kernel(const float* __restrict__ y, const float* __restrict__ gamma,
                          const float* __restrict__ beta, float* __restrict__ out)
{
    const float* r = y + (size_t)blockIdx.x * 768;
    float* o = out + (size_t)blockIdx.x * 768;
    const int tid = threadIdx.x, lane = tid & 31, warp = tid >> 5;
    __shared__ float sred[8];
    __shared__ float sbc;

    float v[3];
    float s = 0.f;
#pragma unroll
    for (int i = 0; i < 3; i++) { v[i] = r[tid + i * 256]; s += v[i]; }
#pragma unroll
    for (int oo = 16; oo; oo >>= 1) s += __shfl_xor_sync(0xffffffffu, s, oo);
    if (lane == 0) sred[warp] = s;
    __syncthreads();
    if (tid == 0) {
        float m = 0.f;
        for (int i = 0; i < 8; i++) m += sred[i];
        sbc = m * (1.f / 768.f);
    }
    __syncthreads();
    float mean = sbc;

    float q = 0.f;
#pragma unroll
    for (int i = 0; i < 3; i++) { float d = v[i] - mean; q += d * d; }
#pragma unroll
    for (int oo = 16; oo; oo >>= 1) q += __shfl_xor_sync(0xffffffffu, q, oo);
    if (lane == 0) sred[warp] = q;
    __syncthreads();
    if (tid == 0) {
        float m = 0.f;
        for (int i = 0; i < 8; i++) m += sred[i];
        sbc = rsqrtf(m * (1.f / 768.f) + 1e-5f);
    }
    __syncthreads();
    float rstd = sbc;
#pragma unroll
    for (int i = 0; i < 3; i++) {
        int c = tid + i * 256;
        o[c] = (v[i] - mean) * rstd * gamma[c] + beta[c];
    }
}

// ---------------------------------------------------------------------------
extern "C" void kernel_launch(void* const* d_in, const int* in_sizes, int n_in,
                              void* d_out, int out_size)
{
    const float* x      = (const float*)d_in[0];
    const float* w_qkv  = (const float*)d_in[1];
    const float* b_qkv  = (const float*)d_in[2];
    const float* w_proj = (const float*)d_in[3];
    const float* b_proj = (const float*)d_in[4];
    const float* gamma  = (const float*)d_in[5];
    const float* beta   = (const float*)d_in[6];
    const float* qe_w1  = (const float*)d_in[7];
    const float* qe_b1  = (const float*)d_in[8];
    const float* qe_w2  = (const float*)d_in[9];
    const float* qe_b2  = (const float*)d_in[10];
    const float* ke_w1  = (const float*)d_in[11];
    const float* ke_b1  = (const float*)d_in[12];
    const float* ke_w2  = (const float*)d_in[13];
    const float* ke_b2  = (const float*)d_in[14];
    // d_in[15..18] = ve_* : dead code in the reference, never used
    const float* gate   = (const float*)d_in[19];
    const float* ent    = (const float*)d_in[20];
    const float* md_w1  = (const float*)d_in[21];
    const float* md_b1  = (const float*)d_in[22];
    const float* md_w2  = (const float*)d_in[23];
    const float* md_b2  = (const float*)d_in[24];
    const float* gumbel = (const float*)d_in[25];
    float* out = (float*)d_out;

    float *qkv, *eqv, *ekv, *scores, *quant, *clas, *fused, *yb, *xmean, *fw;
    cudaGetSymbolAddress((void**)&qkv,    g_qkv);
    cudaGetSymbolAddress((void**)&eqv,    g_eq);
    cudaGetSymbolAddress((void**)&ekv,    g_ek);
    cudaGetSymbolAddress((void**)&scores, g_scores);
    cudaGetSymbolAddress((void**)&quant,  g_quantum);
    cudaGetSymbolAddress((void**)&clas,   g_classical);
    cudaGetSymbolAddress((void**)&fused,  g_fused);
    cudaGetSymbolAddress((void**)&yb,     g_y);
    cudaGetSymbolAddress((void**)&xmean,  g_xmean);
    cudaGetSymbolAddress((void**)&fw,     g_fw);

    // 1) QKV projection: [8192,768] @ [768,2304] + bias
    sgemm128<<<dim3(18, 64), 256>>>(x, w_qkv, b_qkv, nullptr, qkv, 768, 768, 2304, 2304);

    // 2) quantum path
    embed_kernel<<<8192, 256>>>(qkv, qe_w1, qe_b1, qe_w2, qe_b2, eqv, 0);
    embed_kernel<<<8192, 256>>>(qkv, ke_w1, ke_b1, ke_w2, ke_b2, ekv, 1);
    quantum_kernel<<<8192, 256>>>(qkv, eqv, ekv, gate, ent, md_w1, md_b1, md_w2, md_b2,
                                  gumbel, quant);

    // 3) classical attention
    scores_kernel<<<dim3(8, 8, 64), 256>>>(qkv, scores);
    softmax1024<<<65536, 256>>>(scores);
    pv_kernel<<<dim3(1, 16, 64), 256>>>(scores, qkv, clas);

    // 4) fusion gate
    xmean_kernel<<<24, 256>>>(x, xmean);
    fw_kernel<<<24, 256>>>(xmean, w_proj, b_proj, fw);
    blend_kernel<<<24576, 256>>>(fw, quant, clas, fused);

    // 5) output projection + residual, then layernorm
    sgemm128<<<dim3(6, 64), 256>>>(fused, w_proj, b_proj, x, yb, 768, 768, 768, 768);
    ln_kernel<<<8192, 256>>>(yb, gamma, beta, out);
}

// round 2
// speedup vs baseline: 1.1103x; 1.1103x over previous
#include <cuda_runtime.h>
#include <math.h>

// ---------------------------------------------------------------------------
// Shapes (fixed): B=8, N=1024, C=768, H=8, D=96, Q=8
// ---------------------------------------------------------------------------

// Scratch buffers (allocation-free rule: __device__ globals)
__device__ float g_qkv[8192 * 2304];          // [B*N, 3*C]  (B,N,3,H,D)
__device__ float g_eq[65536 * 16];            // embed(q) raw e vector per token
__device__ float g_ek[65536 * 16];            // embed(k)
__device__ float g_scores[67108864];          // [B*H, 1024, 1024]
__device__ float g_quantum[8192 * 768];       // [B,N,C]
__device__ float g_classical[8192 * 768];     // [B,N,C]
__device__ float g_fused[8192 * 768];
__device__ float g_y[8192 * 768];
__device__ float g_xmean[8 * 768];
__device__ float g_fw[8 * 768];

// ---------------------------------------------------------------------------
// Generic 128x128x16 SGEMM (row-major NN), optional bias (per-col) + residual.
// Requires: M%128==0, N%128==0, K%16==0, lda/ldb multiples of 4.
// ---------------------------------------------------------------------------
__global__ void sgemm128(const float* __restrict__ A, const float* __restrict__ B,
                         const float* __restrict__ bias, const float* __restrict__ resid,
                         float* __restrict__ C, int K, int lda, int ldb, int ldc)
{
    __shared__ float As[16][132];
    __shared__ float Bs[16][132];
    const int tid = threadIdx.x;
    const int tx = tid & 15, ty = tid >> 4;
    const size_t rowBase = (size_t)blockIdx.y * 128;
    const size_t colBase = (size_t)blockIdx.x * 128;

    float acc[8][8];
#pragma unroll
    for (int i = 0; i < 8; i++)
#pragma unroll
        for (int j = 0; j < 8; j++) acc[i][j] = 0.f;

    for (int k0 = 0; k0 < K; k0 += 16) {
#pragma unroll
        for (int i = 0; i < 2; i++) {
            int s = tid + i * 256;
            int r = s >> 2, c = (s & 3) << 2;
            float4 va = *(const float4*)(A + (rowBase + r) * lda + k0 + c);
            As[c + 0][r] = va.x; As[c + 1][r] = va.y;
            As[c + 2][r] = va.z; As[c + 3][r] = va.w;
            int rb = s >> 5, cb = (s & 31) << 2;
            float4 vb = *(const float4*)(B + (size_t)(k0 + rb) * ldb + colBase + cb);
            *(float4*)&Bs[rb][cb] = vb;
        }
        __syncthreads();
#pragma unroll
        for (int kk = 0; kk < 16; kk++) {
            float a[8], b[8];
#pragma unroll
            for (int i = 0; i < 8; i++) a[i] = As[kk][ty * 8 + i];
#pragma unroll
            for (int j = 0; j < 8; j++) b[j] = Bs[kk][tx * 8 + j];
#pragma unroll
            for (int i = 0; i < 8; i++)
#pragma unroll
                for (int j = 0; j < 8; j++) acc[i][j] += a[i] * b[j];
        }
        __syncthreads();
    }
#pragma unroll
    for (int i = 0; i < 8; i++) {
        size_t row = rowBase + ty * 8 + i;
#pragma unroll
        for (int j = 0; j < 8; j++) {
            size_t col = colBase + tx * 8 + j;
            float v = acc[i][j];
            if (bias)  v += bias[col];
            if (resid) v += resid[row * ldc + col];
            C[row * ldc + col] = v;
        }
    }
}

// ---------------------------------------------------------------------------
// scores[bh,n,m] = scale * sum_d q[b,h,n,d] * k[b,h,m,d]   (batched NT GEMM)
// ---------------------------------------------------------------------------
__global__ void scores_kernel(const float* __restrict__ qkv, float* __restrict__ scores)
{
    __shared__ float As[16][132];
    __shared__ float Bs[16][132];
    const int bh = blockIdx.z, b = bh >> 3, h = bh & 7;
    const float* qp = qkv + (size_t)b * 1024 * 2304 + h * 96;
    const float* kp = qp + 768;
    float* out = scores + (size_t)bh * 1024 * 1024;
    const int tid = threadIdx.x, tx = tid & 15, ty = tid >> 4;
    const int rowBase = blockIdx.y * 128, colBase = blockIdx.x * 128;

    float acc[8][8];
#pragma unroll
    for (int i = 0; i < 8; i++)
#pragma unroll
        for (int j = 0; j < 8; j++) acc[i][j] = 0.f;

    for (int k0 = 0; k0 < 96; k0 += 16) {
#pragma unroll
        for (int i = 0; i < 2; i++) {
            int s = tid + i * 256;
            int r = s >> 2, c = (s & 3) << 2;
            float4 va = *(const float4*)(qp + (size_t)(rowBase + r) * 2304 + k0 + c);
            As[c + 0][r] = va.x; As[c + 1][r] = va.y;
            As[c + 2][r] = va.z; As[c + 3][r] = va.w;
            float4 vb = *(const float4*)(kp + (size_t)(colBase + r) * 2304 + k0 + c);
            Bs[c + 0][r] = vb.x; Bs[c + 1][r] = vb.y;
            Bs[c + 2][r] = vb.z; Bs[c + 3][r] = vb.w;
        }
        __syncthreads();
#pragma unroll
        for (int kk = 0; kk < 16; kk++) {
            float a[8], bb[8];
#pragma unroll
            for (int i = 0; i < 8; i++) a[i] = As[kk][ty * 8 + i];
#pragma unroll
            for (int j = 0; j < 8; j++) bb[j] = Bs[kk][tx * 8 + j];
#pragma unroll
            for (int i = 0; i < 8; i++)
#pragma unroll
                for (int j = 0; j < 8; j++) acc[i][j] += a[i] * bb[j];
        }
        __syncthreads();
    }
    const float scale = 0.10206207261596575f;  // 96^-0.5
#pragma unroll
    for (int i = 0; i < 8; i++) {
        size_t row = rowBase + ty * 8 + i;
#pragma unroll
        for (int j = 0; j < 8; j++) {
            size_t col = colBase + tx * 8 + j;
            out[row * 1024 + col] = acc[i][j] * scale;
        }
    }
}

// ---------------------------------------------------------------------------
// Row softmax over 1024 elements, in place. One block (256 thr) per row.
// ---------------------------------------------------------------------------
__global__ void softmax1024(float* __restrict__ scores)
{
    float* row = scores + (size_t)blockIdx.x * 1024;
    const int tid = threadIdx.x, lane = tid & 31, warp = tid >> 5;
    __shared__ float sred[8];
    __shared__ float sbc;

    float v[4];
    float mx = -1e30f;
#pragma unroll
    for (int i = 0; i < 4; i++) { v[i] = row[tid + i * 256]; mx = fmaxf(mx, v[i]); }
#pragma unroll
    for (int o = 16; o; o >>= 1) mx = fmaxf(mx, __shfl_xor_sync(0xffffffffu, mx, o));
    if (lane == 0) sred[warp] = mx;
    __syncthreads();
    if (tid == 0) {
        float m = sred[0];
        for (int i = 1; i < 8; i++) m = fmaxf(m, sred[i]);
        sbc = m;
    }
    __syncthreads();
    mx = sbc;

    float s = 0.f;
#pragma unroll
    for (int i = 0; i < 4; i++) { v[i] = __expf(v[i] - mx); s += v[i]; }
#pragma unroll
    for (int o = 16; o; o >>= 1) s += __shfl_xor_sync(0xffffffffu, s, o);
    if (lane == 0) sred[warp] = s;
    __syncthreads();
    if (tid == 0) {
        float m = 0.f;
        for (int i = 0; i < 8; i++) m += sred[i];
        sbc = m;
    }
    __syncthreads();
    float inv = __frcp_rn(sbc);
#pragma unroll
    for (int i = 0; i < 4; i++) row[tid + i * 256] = v[i] * inv;
}

// ---------------------------------------------------------------------------
// classical[b,n,h*96+d] = sum_m P[bh,n,m] * v[b,h,m,d]
// BM=128, BN=96 (full D), BK=16; 256 threads, 8x6 microtile.
// ---------------------------------------------------------------------------
__global__ void pv_kernel(const float* __restrict__ scores, const float* __restrict__ qkv,
                          float* __restrict__ classical)
{
    __shared__ float As[16][132];
    __shared__ float Bs[16][96];
    const int bh = blockIdx.z, b = bh >> 3, h = bh & 7;
    const float* P = scores + (size_t)bh * 1024 * 1024;
    const float* V = qkv + (size_t)b * 1024 * 2304 + 1536 + h * 96;
    float* out = classical + (size_t)b * 1024 * 768 + h * 96;
    const int tid = threadIdx.x, tx = tid & 15, ty = tid >> 4;
    const int rowBase = blockIdx.y * 128;

    float acc[8][6];
#pragma unroll
    for (int i = 0; i < 8; i++)
#pragma unroll
        for (int j = 0; j < 6; j++) acc[i][j] = 0.f;

    for (int k0 = 0; k0 < 1024; k0 += 16) {
#pragma unroll
        for (int i = 0; i < 2; i++) {
            int s = tid + i * 256;
            int r = s >> 2, c = (s & 3) << 2;
            float4 va = *(const float4*)(P + (size_t)(rowBase + r) * 1024 + k0 + c);
            As[c + 0][r] = va.x; As[c + 1][r] = va.y;
            As[c + 2][r] = va.z; As[c + 3][r] = va.w;
        }
        {
            int r = tid >> 4, cb = (tid & 15) * 6;
#pragma unroll
            for (int u = 0; u < 6; u++)
                Bs[r][cb + u] = V[(size_t)(k0 + r) * 2304 + cb + u];
        }
        __syncthreads();
#pragma unroll
        for (int kk = 0; kk < 16; kk++) {
            float a[8], bb[6];
#pragma unroll
            for (int i = 0; i < 8; i++) a[i] = As[kk][ty * 8 + i];
#pragma unroll
            for (int j = 0; j < 6; j++) bb[j] = Bs[kk][tx * 6 + j];
#pragma unroll
            for (int i = 0; i < 8; i++)
#pragma unroll
                for (int j = 0; j < 6; j++) acc[i][j] += a[i] * bb[j];
        }
        __syncthreads();
    }
#pragma unroll
    for (int i = 0; i < 8; i++) {
        size_t row = rowBase + ty * 8 + i;
#pragma unroll
        for (int j = 0; j < 6; j++)
            out[row * 768 + tx * 6 + j] = acc[i][j];
    }
}

// ---------------------------------------------------------------------------
// Embedding MLP: e = relu(h @ w1 + b1) @ w2 + b2  (h: 96, hid 64, out 16)
// warp per token; which=0 -> q, which=1 -> k slice of qkv.
// ---------------------------------------------------------------------------
__global__ void embed_kernel(const float* __restrict__ qkv,
                             const float* __restrict__ w1, const float* __restrict__ b1,
                             const float* __restrict__ w2, const float* __restrict__ b2,
                             float* __restrict__ eout, int which)
{
    __shared__ float sw1[96 * 64];
    __shared__ float sw2[64 * 16];
    __shared__ float sb1[64];
    __shared__ float sb2[16];
    __shared__ float sh[8][64];
    const int tid = threadIdx.x;
    for (int i = tid; i < 96 * 64; i += 256) sw1[i] = w1[i];
    for (int i = tid; i < 64 * 16; i += 256) sw2[i] = w2[i];
    if (tid < 64) sb1[tid] = b1[tid];
    if (tid < 16) sb2[tid] = b2[tid];
    __syncthreads();

    const int warp = tid >> 5, lane = tid & 31;
    const int t = blockIdx.x * 8 + warp;       // token in [0, 65536)
    const int b = t >> 13, h = (t >> 10) & 7, n = t & 1023;
    const float* xp = qkv + (size_t)(b * 1024 + n) * 2304 + which * 768 + h * 96;
    float x0 = xp[lane], x1 = xp[lane + 32], x2 = xp[lane + 64];

    float acc0 = sb1[lane], acc1 = sb1[lane + 32];
#pragma unroll
    for (int i = 0; i < 32; i++) {
        float xv = __shfl_sync(0xffffffffu, x0, i);
        acc0 += xv * sw1[i * 64 + lane];
        acc1 += xv * sw1[i * 64 + 32 + lane];
    }
#pragma unroll
    for (int i = 0; i < 32; i++) {
        float xv = __shfl_sync(0xffffffffu, x1, i);
        acc0 += xv * sw1[(32 + i) * 64 + lane];
        acc1 += xv * sw1[(32 + i) * 64 + 32 + lane];
    }
#pragma unroll
    for (int i = 0; i < 32; i++) {
        float xv = __shfl_sync(0xffffffffu, x2, i);
        acc0 += xv * sw1[(64 + i) * 64 + lane];
        acc1 += xv * sw1[(64 + i) * 64 + 32 + lane];
    }
    sh[warp][lane] = fmaxf(acc0, 0.f);
    sh[warp][lane + 32] = fmaxf(acc1, 0.f);
    __syncwarp();
    if (lane < 16) {
        float o = sb2[lane];
#pragma unroll
        for (int j = 0; j < 64; j++) o += sh[warp][j] * sw2[j * 16 + lane];
        eout[(size_t)t * 16 + lane] = o;
    }
}

// ---------------------------------------------------------------------------
// Quantum path: state = qq + kk -> variational(2 layers) -> probs -> gumbel
// softmax -> MLP(8->64->96) -> quantum_out = attn_w * v   (warp per token)
// All transcendentals via MUFU fast intrinsics (rel_err budget is 1e-3).
// ---------------------------------------------------------------------------
__global__ void quantum_kernel(const float* __restrict__ qkv,
                               const float* __restrict__ eq, const float* __restrict__ ek,
                               const float* __restrict__ gate, const float* __restrict__ ent,
                               const float* __restrict__ mdw1, const float* __restrict__ mdb1,
                               const float* __restrict__ mdw2, const float* __restrict__ mdb2,
                               const float* __restrict__ gumbel, float* __restrict__ quantum)
{
    __shared__ float sw1[8 * 64];
    __shared__ float sw2[64 * 96];
    __shared__ float sb1[64];
    __shared__ float sb2[96];
    __shared__ float sg[48];
    __shared__ float se[14];
    __shared__ float sh[8][64];
    const int tid = threadIdx.x;
    for (int i = tid; i < 8 * 64; i += 256) sw1[i] = mdw1[i];
    for (int i = tid; i < 64 * 96; i += 256) sw2[i] = mdw2[i];
    if (tid < 64) sb1[tid] = mdb1[tid];
    if (tid < 96) sb2[tid] = mdb2[tid];
    if (tid < 48) sg[tid] = gate[tid];
    if (tid < 14) se[tid] = ent[tid];
    __syncthreads();

    const int warp = tid >> 5, lane = tid & 31;
    const int t = blockIdx.x * 8 + warp;
    const int b = t >> 13, h = (t >> 10) & 7, n = t & 1023;

    const float* eqp = eq + (size_t)t * 16;
    const float* ekp = ek + (size_t)t * 16;
    float ev[16];
    float sr[8], si[8];

    // qq
#pragma unroll
    for (int i = 0; i < 16; i++) ev[i] = eqp[i];
    {
        float mx = ev[0];
#pragma unroll
        for (int i = 1; i < 8; i++) mx = fmaxf(mx, ev[i]);
        float a[8]; float ssum = 0.f;
#pragma unroll
        for (int i = 0; i < 8; i++) { a[i] = __expf(ev[i] - mx); ssum += a[i]; }
        float inv = __frcp_rn(ssum);
#pragma unroll
        for (int i = 0; i < 8; i++) {
            float amp = a[i] * inv, ph = ev[8 + i];
            sr[i] = amp * __cosf(ph);
            si[i] = amp * __sinf(ph);
        }
    }
    // + kk
#pragma unroll
    for (int i = 0; i < 16; i++) ev[i] = ekp[i];
    {
        float mx = ev[0];
#pragma unroll
        for (int i = 1; i < 8; i++) mx = fmaxf(mx, ev[i]);
        float a[8]; float ssum = 0.f;
#pragma unroll
        for (int i = 0; i < 8; i++) { a[i] = __expf(ev[i] - mx); ssum += a[i]; }
        float inv = __frcp_rn(ssum);
#pragma unroll
        for (int i = 0; i < 8; i++) {
            float amp = a[i] * inv, ph = ev[8 + i];
            sr[i] += amp * __cosf(ph);
            si[i] += amp * __sinf(ph);
        }
    }

    // variational (depth 2)
#pragma unroll
    for (int l = 0; l < 2; l++) {
        float nr[8], ni[8];
#pragma unroll
        for (int i = 0; i < 8; i++) {
            float ry = sg[(l * 8 + i) * 3 + 1];
            float rz = sg[(l * 8 + i) * 3 + 2];
            float cz = __cosf(rz), sz = __sinf(rz), f = __cosf(ry * 0.5f);
            nr[i] = (sr[i] * cz - si[i] * sz) * f;
            ni[i] = (sr[i] * sz + si[i] * cz) * f;
        }
        sr[0] = nr[0]; si[0] = ni[0];
#pragma unroll
        for (int i = 1; i < 8; i++) {
            float s_ = __frcp_rn(1.f + __expf(-se[l * 7 + i - 1]));
            sr[i] = nr[i] + s_ * nr[i - 1];
            si[i] = ni[i] + s_ * ni[i - 1];
        }
    }

    // probs softmax, gumbel softmax (T=0.5)
    float p[8];
#pragma unroll
    for (int i = 0; i < 8; i++) p[i] = sr[i] * sr[i] + si[i] * si[i];
    float mx = p[0];
#pragma unroll
    for (int i = 1; i < 8; i++) mx = fmaxf(mx, p[i]);
    float ssum = 0.f;
#pragma unroll
    for (int i = 0; i < 8; i++) { p[i] = __expf(p[i] - mx); ssum += p[i]; }
    float inv = __frcp_rn(ssum);
    const float* gp = gumbel + (size_t)t * 8;
    float lg[8];
    float mx2 = -1e30f;
#pragma unroll
    for (int i = 0; i < 8; i++) {
        lg[i] = (__logf(p[i] * inv + 1e-10f) + gp[i]) * 2.f;
        mx2 = fmaxf(mx2, lg[i]);
    }
    float s2 = 0.f;
#pragma unroll
    for (int i = 0; i < 8; i++) { lg[i] = __expf(lg[i] - mx2); s2 += lg[i]; }
    float inv2 = __frcp_rn(s2);
    float meas[8];
#pragma unroll
    for (int i = 0; i < 8; i++) meas[i] = lg[i] * inv2;

    // MLP: 8 -> 64 (relu) -> 96 ; then * v, scatter to [B,N,C]
    float h0 = sb1[lane], h1 = sb1[lane + 32];
#pragma unroll
    for (int q = 0; q < 8; q++) {
        h0 += meas[q] * sw1[q * 64 + lane];
        h1 += meas[q] * sw1[q * 64 + 32 + lane];
    }
    sh[warp][lane] = fmaxf(h0, 0.f);
    sh[warp][lane + 32] = fmaxf(h1, 0.f);
    __syncwarp();

    const float* vp = qkv + (size_t)(b * 1024 + n) * 2304 + 1536 + h * 96;
    float* outp = quantum + (size_t)(b * 1024 + n) * 768 + h * 96;
#pragma unroll
    for (int u = 0; u < 3; u++) {
        int d = lane + u * 32;
        float o = sb2[d];
#pragma unroll
        for (int j = 0; j < 64; j++) o += sh[warp][j] * sw2[j * 96 + d];
        outp[d] = o * vp[d];
    }
}

// ---------------------------------------------------------------------------
// x mean over N, fw = sigmoid(xmean @ w_proj + b_proj), blend, layernorm
// ---------------------------------------------------------------------------
__global__ void xmean_kernel(const float* __restrict__ x, float* __restrict__ xmean)
{
    int idx = blockIdx.x * blockDim.x + threadIdx.x;
    if (idx >= 8 * 768) return;
    int b = idx / 768, c = idx % 768;
    const float* p = x + (size_t)b * 1024 * 768 + c;
    float s = 0.f;
    for (int n = 0; n < 1024; n++) s += p[(size_t)n * 768];
    xmean[idx] = s * (1.f / 1024.f);
}

__global__ void fw_kernel(const float* __restrict__ xmean, const float* __restrict__ wproj,
                          const float* __restrict__ bproj, float* __restrict__ fw)
{
    int idx = blockIdx.x * blockDim.x + threadIdx.x;
    if (idx >= 8 * 768) return;
    int b = idx / 768, j = idx % 768;
    const float* xm = xmean + b * 768;
    float s = bproj[j];
    for (int c = 0; c < 768; c++) s += xm[c] * wproj[(size_t)c * 768 + j];
    fw[idx] = __frcp_rn(1.f + __expf(-s));
}

__global__ void blend_kernel(const float* __restrict__ fw, const float* __restrict__ quant,
                             const float* __restrict__ clas, float* __restrict__ fused)
{
    size_t idx = (size_t)blockIdx.x * blockDim.x + threadIdx.x;
    if (idx >= (size_t)8192 * 768) return;
    int m = (int)(idx / 768);
    int b = m >> 10;
    int c = (int)(idx % 768);
    float f = fw[b * 768 + c];
    fused[idx] = f * quant[idx] + (1.f - f) * clas[idx];
}

__global__ void ln_kernel(const float* __restrict__ y, const float* __restrict__ gamma,
                          const float* __restrict__ beta, float* __restrict__ out)
{
    const float* r = y + (size_t)blockIdx.x * 768;
    float* o = out + (size_t)blockIdx.x * 768;
    const int tid = threadIdx.x, lane = tid & 31, warp = tid >> 5;
    __shared__ float sred[8];
    __shared__ float sbc;

    float v[3];
    float s = 0.f;
#pragma unroll
    for (int i = 0; i < 3; i++) { v[i] = r[tid + i * 256]; s += v[i]; }
#pragma unroll
    for (int oo = 16; oo; oo >>= 1) s += __shfl_xor_sync(0xffffffffu, s, oo);
    if (lane == 0) sred[warp] = s;
    __syncthreads();
    if (tid == 0) {
        float m = 0.f;
        for (int i = 0; i < 8; i++) m += sred[i];
        sbc = m * (1.f / 768.f);
    }
    __syncthreads();
    float mean = sbc;

    float q = 0.f;
#pragma unroll
    for (int i = 0; i < 3; i++) { float d = v[i] - mean; q += d * d; }
#pragma unroll
    for (int oo = 16; oo; oo >>= 1) q += __shfl_xor_sync(0xffffffffu, q, oo);
    if (lane == 0) sred[warp] = q;
    __syncthreads();
    if (tid == 0) {
        float m = 0.f;
        for (int i = 0; i < 8; i++) m += sred[i];
        sbc = rsqrtf(m * (1.f / 768.f) + 1e-5f);
    }
    __syncthreads();
    float rstd = sbc;
#pragma unroll
    for (int i = 0; i < 3; i++) {
        int c = tid + i * 256;
        o[c] = (v[i] - mean) * rstd * gamma[c] + beta[c];
    }
}

// ---------------------------------------------------------------------------
extern "C" void kernel_launch(void* const* d_in, const int* in_sizes, int n_in,
                              void* d_out, int out_size)
{
    const float* x      = (const float*)d_in[0];
    const float* w_qkv  = (const float*)d_in[1];
    const float* b_qkv  = (const float*)d_in[2];
    const float* w_proj = (const float*)d_in[3];
    const float* b_proj = (const float*)d_in[4];
    const float* gamma  = (const float*)d_in[5];
    const float* beta   = (const float*)d_in[6];
    const float* qe_w1  = (const float*)d_in[7];
    const float* qe_b1  = (const float*)d_in[8];
    const float* qe_w2  = (const float*)d_in[9];
    const float* qe_b2  = (const float*)d_in[10];
    const float* ke_w1  = (const float*)d_in[11];
    const float* ke_b1  = (const float*)d_in[12];
    const float* ke_w2  = (const float*)d_in[13];
    const float* ke_b2  = (const float*)d_in[14];
    // d_in[15..18] = ve_* : dead code in the reference, never used
    const float* gate   = (const float*)d_in[19];
    const float* ent    = (const float*)d_in[20];
    const float* md_w1  = (const float*)d_in[21];
    const float* md_b1  = (const float*)d_in[22];
    const float* md_w2  = (const float*)d_in[23];
    const float* md_b2  = (const float*)d_in[24];
    const float* gumbel = (const float*)d_in[25];
    float* out = (float*)d_out;

    float *qkv, *eqv, *ekv, *scores, *quant, *clas, *fused, *yb, *xmean, *fw;
    cudaGetSymbolAddress((void**)&qkv,    g_qkv);
    cudaGetSymbolAddress((void**)&eqv,    g_eq);
    cudaGetSymbolAddress((void**)&ekv,    g_ek);
    cudaGetSymbolAddress((void**)&scores, g_scores);
    cudaGetSymbolAddress((void**)&quant,  g_quantum);
    cudaGetSymbolAddress((void**)&clas,   g_classical);
    cudaGetSymbolAddress((void**)&fused,  g_fused);
    cudaGetSymbolAddress((void**)&yb,     g_y);
    cudaGetSymbolAddress((void**)&xmean,  g_xmean);
    cudaGetSymbolAddress((void**)&fw,     g_fw);

    // 1) QKV projection: [8192,768] @ [768,2304] + bias
    sgemm128<<<dim3(18, 64), 256>>>(x, w_qkv, b_qkv, nullptr, qkv, 768, 768, 2304, 2304);

    // 2) quantum path
    embed_kernel<<<8192, 256>>>(qkv, qe_w1, qe_b1, qe_w2, qe_b2, eqv, 0);
    embed_kernel<<<8192, 256>>>(qkv, ke_w1, ke_b1, ke_w2, ke_b2, ekv, 1);
    quantum_kernel<<<8192, 256>>>(qkv, eqv, ekv, gate, ent, md_w1, md_b1, md_w2, md_b2,
                                  gumbel, quant);

    // 3) classical attention
    scores_kernel<<<dim3(8, 8, 64), 256>>>(qkv, scores);
    softmax1024<<<65536, 256>>>(scores);
    pv_kernel<<<dim3(1, 8, 64), 256>>>(scores, qkv, clas);

    // 4) fusion gate
    xmean_kernel<<<24, 256>>>(x, xmean);
    fw_kernel<<<24, 256>>>(xmean, w_proj, b_proj, fw);
    blend_kernel<<<24576, 256>>>(fw, quant, clas, fused);

    // 5) output projection + residual, then layernorm
    sgemm128<<<dim3(6, 64), 256>>>(fused, w_proj, b_proj, x, yb, 768, 768, 768, 768);
    ln_kernel<<<8192, 256>>>(yb, gamma, beta, out);
}